// round 2
// baseline (speedup 1.0000x reference)
#include <cuda_runtime.h>
#include <cstdint>

// Problem constants
#define BB 16
#define LL 2048
#define DD 64
#define BQ 16          // q rows per CTA
#define TK 128         // k cols per tile
#define NT (LL / TK)   // 16 tiles
#define PITCH 2052     // score row pitch (floats), mult of 4
#define NTHREADS 512

#define SC_WORDS (BQ * PITCH)     // 32832
#define QS_WORDS (BQ * DD)        // 1024  (swizzled)
#define KS_WORDS (2 * TK * DD)    // 16384 (double buffered, swizzled)
#define SMEM_BYTES ((SC_WORDS + QS_WORDS + KS_WORDS) * 4)   // ~200.9 KB

__device__ __forceinline__ void fma2(unsigned long long& acc,
                                     unsigned long long a,
                                     unsigned long long b) {
    asm volatile("fma.rn.f32x2 %0, %1, %2, %0;" : "+l"(acc) : "l"(a), "l"(b));
}

__device__ __forceinline__ float hsum2(unsigned long long a) {
    float lo, hi;
    asm("mov.b64 {%0, %1}, %2;" : "=f"(lo), "=f"(hi) : "l"(a));
    return lo + hi;
}

__device__ __forceinline__ ulonglong2 lds128(uint32_t addr) {
    ulonglong2 v;
    asm volatile("ld.shared.v2.u64 {%0, %1}, [%2];"
                 : "=l"(v.x), "=l"(v.y) : "r"(addr));
    return v;
}

__device__ __forceinline__ void cp16(uint32_t dst_smem, const float* src) {
    asm volatile("cp.async.cg.shared.global [%0], [%1], 16;\n"
                 :: "r"(dst_smem), "l"(src));
}
__device__ __forceinline__ void cp_commit() {
    asm volatile("cp.async.commit_group;\n");
}
template <int N>
__device__ __forceinline__ void cp_wait() {
    asm volatile("cp.async.wait_group %0;\n" :: "n"(N));
}

__global__ void __launch_bounds__(NTHREADS, 1)
attn_kernel(const float* __restrict__ q,
            const float* __restrict__ k,
            float* __restrict__ out_attn) {
    extern __shared__ float smem[];
    float* sc = smem;                    // [BQ][PITCH]
    float* qs = smem + SC_WORDS;         // [BQ][64] chunk-swizzled
    float* ks = qs + QS_WORDS;           // [2][TK][64] chunk-swizzled

    const int b  = blockIdx.y;
    const int qt = blockIdx.x;

    const float* qp = q + ((size_t)b * LL + (size_t)qt * BQ) * DD;
    const float* kp = k + (size_t)b * LL * DD;
    float* outp = out_attn + ((size_t)b * LL + (size_t)qt * BQ) * (size_t)LL;

    const int tid = threadIdx.x;
    const int w   = tid >> 5;
    const int l   = tid & 31;
    const int a   = l >> 2;       // 0..7 -> row pair
    const int bn  = l & 3;        // 0..3 -> col lane
    const int r0  = 2 * a;
    const int r1  = 2 * a + 1;
    const int cb  = w * 8;        // warp col base within tile

    const uint32_t qs_base = (uint32_t)__cvta_generic_to_shared(qs);
    const uint32_t ks_base = (uint32_t)__cvta_generic_to_shared(ks);

    // ---- stage q (swizzled): 256 x 16B chunks ----
    if (tid < 256) {
        int r = tid >> 4, i = tid & 15;
        cp16(qs_base + (uint32_t)(r * 64 + ((i ^ (r >> 1)) << 2)) * 4u,
             qp + (size_t)r * DD + (size_t)i * 4);
    }
    // ---- prefetch k tile 0 (swizzled): 2048 chunks ----
    {
        #pragma unroll
        for (int rep = 0; rep < 4; rep++) {
            int idx = tid + rep * NTHREADS;
            int c = idx >> 4, i = idx & 15;
            cp16(ks_base + (uint32_t)(c * 64 + ((i ^ (c & 3)) << 2)) * 4u,
                 kp + (size_t)c * DD + (size_t)i * 4);
        }
        cp_commit();
    }

    // per-lane base addresses (bytes)
    const uint32_t q0b = qs_base + (uint32_t)(r0 * 64) * 4u;
    const uint32_t q1b = qs_base + (uint32_t)(r1 * 64) * 4u;

    // ---- mainloop over 16 k tiles ----
    for (int kt = 0; kt < NT; kt++) {
        if (kt + 1 < NT) {
            const float* kn = kp + (size_t)(kt + 1) * TK * DD;
            uint32_t dbuf = ks_base + (uint32_t)(((kt + 1) & 1) * TK * DD) * 4u;
            #pragma unroll
            for (int rep = 0; rep < 4; rep++) {
                int idx = tid + rep * NTHREADS;
                int c = idx >> 4, i = idx & 15;
                cp16(dbuf + (uint32_t)(c * 64 + ((i ^ (c & 3)) << 2)) * 4u,
                     kn + (size_t)c * DD + (size_t)i * 4);
            }
            cp_commit();
            cp_wait<1>();
        } else {
            cp_wait<0>();
        }
        __syncthreads();

        const uint32_t kb = ks_base + (uint32_t)((kt & 1) * TK * DD) * 4u;
        const uint32_t kc0 = kb + (uint32_t)(cb + bn) * 256u;
        const uint32_t kc1 = kb + (uint32_t)(cb + bn + 4) * 256u;

        unsigned long long acc00 = 0ull, acc01 = 0ull;
        unsigned long long acc10 = 0ull, acc11 = 0ull;

        #pragma unroll
        for (int i = 0; i < 16; i++) {
            const uint32_t sq = (uint32_t)((i ^ a) << 4);
            const uint32_t sk = (uint32_t)((i ^ bn) << 4);
            ulonglong2 q0 = lds128(q0b + sq);
            ulonglong2 q1 = lds128(q1b + sq);
            ulonglong2 k0 = lds128(kc0 + sk);
            ulonglong2 k1 = lds128(kc1 + sk);
            fma2(acc00, q0.x, k0.x); fma2(acc00, q0.y, k0.y);
            fma2(acc01, q0.x, k1.x); fma2(acc01, q0.y, k1.y);
            fma2(acc10, q1.x, k0.x); fma2(acc10, q1.y, k0.y);
            fma2(acc11, q1.x, k1.x); fma2(acc11, q1.y, k1.y);
        }

        const int col0 = kt * TK + cb + bn;
        const int col1 = col0 + 4;
        sc[r0 * PITCH + col0] = hsum2(acc00);
        sc[r0 * PITCH + col1] = hsum2(acc01);
        sc[r1 * PITCH + col0] = hsum2(acc10);
        sc[r1 * PITCH + col1] = hsum2(acc11);

        __syncthreads();
    }

    // ---- softmax: warp w owns row w ----
    {
        float* row = sc + w * PITCH;
        float mx = -1e30f;
        #pragma unroll 8
        for (int i = l; i < LL; i += 32)
            mx = fmaxf(mx, row[i]);
        #pragma unroll
        for (int o = 16; o > 0; o >>= 1)
            mx = fmaxf(mx, __shfl_xor_sync(0xFFFFFFFFu, mx, o));

        float sum = 0.0f;
        #pragma unroll 8
        for (int i = l; i < LL; i += 32) {
            float e = __expf(row[i] - mx);
            row[i] = e;
            sum += e;
        }
        #pragma unroll
        for (int o = 16; o > 0; o >>= 1)
            sum += __shfl_xor_sync(0xFFFFFFFFu, sum, o);

        float inv = 1.0f / sum;
        float* orow = outp + (size_t)w * LL;
        #pragma unroll 8
        for (int i = l; i < LL; i += 32)
            orow[i] = row[i] * inv;
    }
}

extern "C" void kernel_launch(void* const* d_in, const int* in_sizes, int n_in,
                              void* d_out, int out_size) {
    const float* q = (const float*)d_in[0];
    const float* k = (const float*)d_in[1];
    const float* v = (const float*)d_in[2];
    float* out = (float*)d_out;

    const size_t v_elems = (size_t)BB * LL * DD;
    cudaMemcpyAsync(out, v, v_elems * sizeof(float), cudaMemcpyDeviceToDevice);

    cudaFuncSetAttribute(attn_kernel,
                         cudaFuncAttributeMaxDynamicSharedMemorySize,
                         SMEM_BYTES);

    dim3 grid(LL / BQ, BB);   // (128, 16)
    dim3 block(NTHREADS);
    attn_kernel<<<grid, block, SMEM_BYTES>>>(q, k, out + v_elems);
}

// round 3
// speedup vs baseline: 1.1089x; 1.1089x over previous
#include <cuda_runtime.h>
#include <cstdint>

#define BB 16
#define LL 2048
#define DD 64
#define BQ 16          // q rows per CTA
#define TK 128         // k cols per tile
#define NT (LL / TK)   // 16 tiles
#define PITCH 2052     // score row pitch (floats), mult of 4
#define NTHREADS 256

#define SC_WORDS (BQ * PITCH)     // 32832
#define QS_WORDS (BQ * DD)        // 1024
#define KS_WORDS (2 * TK * DD)    // 16384
#define SMEM_BYTES ((SC_WORDS + QS_WORDS + KS_WORDS) * 4)   // ~201 KB

__device__ __forceinline__ void fma2(unsigned long long& acc,
                                     unsigned long long a,
                                     unsigned long long b) {
    asm volatile("fma.rn.f32x2 %0, %1, %2, %0;" : "+l"(acc) : "l"(a), "l"(b));
}

__device__ __forceinline__ float hsum2(unsigned long long a) {
    float lo, hi;
    asm("mov.b64 {%0, %1}, %2;" : "=f"(lo), "=f"(hi) : "l"(a));
    return lo + hi;
}

__device__ __forceinline__ ulonglong2 lds128(uint32_t addr) {
    ulonglong2 v;
    asm volatile("ld.shared.v2.u64 {%0, %1}, [%2];"
                 : "=l"(v.x), "=l"(v.y) : "r"(addr));
    return v;
}

__device__ __forceinline__ void sts128(uint32_t addr, float4 v) {
    asm volatile("st.shared.v4.f32 [%0], {%1, %2, %3, %4};"
                 :: "r"(addr), "f"(v.x), "f"(v.y), "f"(v.z), "f"(v.w));
}

__device__ __forceinline__ void cp16(uint32_t dst_smem, const float* src) {
    asm volatile("cp.async.cg.shared.global [%0], [%1], 16;\n"
                 :: "r"(dst_smem), "l"(src));
}
__device__ __forceinline__ void cp_commit() {
    asm volatile("cp.async.commit_group;\n");
}
template <int N>
__device__ __forceinline__ void cp_wait() {
    asm volatile("cp.async.wait_group %0;\n" :: "n"(N));
}

__global__ void __launch_bounds__(NTHREADS, 1)
attn_kernel(const float* __restrict__ q,
            const float* __restrict__ k,
            float* __restrict__ out_attn) {
    extern __shared__ float smem[];
    float* sc = smem;                    // [BQ][PITCH]
    float* qs = smem + SC_WORDS;         // [16][64]  swizzled: word r*64 + ((i^r)&15)*4
    float* ks = qs + QS_WORDS;           // [2][128][64] swizzled: word c*64 + ((i^(c>>2))&15)*4

    const int b  = blockIdx.y;
    const int qt = blockIdx.x;

    const float* qp = q + ((size_t)b * LL + (size_t)qt * BQ) * DD;
    const float* kp = k + (size_t)b * LL * DD;
    float* outp = out_attn + ((size_t)b * LL + (size_t)qt * BQ) * (size_t)LL;

    const int tid  = threadIdx.x;
    const int w    = tid >> 5;
    const int l    = tid & 31;
    const int rowg = w >> 2;              // 0..1
    const int colg = w & 3;               // 0..3
    const int rp   = l >> 3;              // 0..3
    const int cq   = l & 7;               // 0..7

    const int r0 = rowg * 8 + rp * 2;
    const int r1 = r0 + 1;
    const int cbase = colg * 32 + cq * 4;  // col within tile, 4 consecutive cols

    const uint32_t qs_base = (uint32_t)__cvta_generic_to_shared(qs);
    const uint32_t ks_base = (uint32_t)__cvta_generic_to_shared(ks);

    // ---- stage q (swizzled): 256 x 16B chunks ----
    {
        int r = tid >> 4, i = tid & 15;
        cp16(qs_base + (uint32_t)(r * 64 + (((i ^ r) & 15) << 2)) * 4u,
             qp + (size_t)r * DD + (size_t)i * 4);
    }
    // ---- prefetch k tile 0 (swizzled): 2048 chunks ----
    {
        #pragma unroll
        for (int rep = 0; rep < 8; rep++) {
            int idx = tid + rep * NTHREADS;
            int c = idx >> 4, i = idx & 15;
            cp16(ks_base + (uint32_t)(c * 64 + (((i ^ (c >> 2)) & 15) << 2)) * 4u,
                 kp + (size_t)c * DD + (size_t)i * 4);
        }
        cp_commit();
    }

    // per-thread fixed pieces
    const uint32_t q0b = qs_base + (uint32_t)(r0 * 64) * 4u;
    const uint32_t q1b = qs_base + (uint32_t)(r1 * 64) * 4u;
    const uint32_t sq0 = (uint32_t)((r0 & 15) << 4);  // XOR pattern for q row r0
    const uint32_t sq1 = (uint32_t)((r1 & 15) << 4);
    const uint32_t skx = (uint32_t)(((cbase >> 2) & 15) << 4);  // same for 4 cols

    for (int kt = 0; kt < NT; kt++) {
        if (kt + 1 < NT) {
            const float* kn = kp + (size_t)(kt + 1) * TK * DD;
            uint32_t dbuf = ks_base + (uint32_t)(((kt + 1) & 1) * TK * DD) * 4u;
            #pragma unroll
            for (int rep = 0; rep < 8; rep++) {
                int idx = tid + rep * NTHREADS;
                int c = idx >> 4, i = idx & 15;
                cp16(dbuf + (uint32_t)(c * 64 + (((i ^ (c >> 2)) & 15) << 2)) * 4u,
                     kn + (size_t)c * DD + (size_t)i * 4);
            }
            cp_commit();
            cp_wait<1>();
        } else {
            cp_wait<0>();
        }
        __syncthreads();

        const uint32_t kb = ks_base + (uint32_t)((kt & 1) * TK * DD) * 4u;
        const uint32_t kc0 = kb + (uint32_t)(cbase + 0) * 256u;
        const uint32_t kc1 = kb + (uint32_t)(cbase + 1) * 256u;
        const uint32_t kc2 = kb + (uint32_t)(cbase + 2) * 256u;
        const uint32_t kc3 = kb + (uint32_t)(cbase + 3) * 256u;

        unsigned long long a00 = 0, a01 = 0, a02 = 0, a03 = 0;
        unsigned long long a10 = 0, a11 = 0, a12 = 0, a13 = 0;

        #pragma unroll
        for (int i = 0; i < 16; i++) {
            const uint32_t oq0 = (uint32_t)(i << 4) ^ sq0;
            const uint32_t oq1 = (uint32_t)(i << 4) ^ sq1;
            const uint32_t ok  = (uint32_t)(i << 4) ^ skx;
            ulonglong2 qv0 = lds128(q0b + oq0);
            ulonglong2 qv1 = lds128(q1b + oq1);
            ulonglong2 k0 = lds128(kc0 + ok);
            ulonglong2 k1 = lds128(kc1 + ok);
            ulonglong2 k2 = lds128(kc2 + ok);
            ulonglong2 k3 = lds128(kc3 + ok);
            fma2(a00, qv0.x, k0.x); fma2(a00, qv0.y, k0.y);
            fma2(a01, qv0.x, k1.x); fma2(a01, qv0.y, k1.y);
            fma2(a02, qv0.x, k2.x); fma2(a02, qv0.y, k2.y);
            fma2(a03, qv0.x, k3.x); fma2(a03, qv0.y, k3.y);
            fma2(a10, qv1.x, k0.x); fma2(a10, qv1.y, k0.y);
            fma2(a11, qv1.x, k1.x); fma2(a11, qv1.y, k1.y);
            fma2(a12, qv1.x, k2.x); fma2(a12, qv1.y, k2.y);
            fma2(a13, qv1.x, k3.x); fma2(a13, qv1.y, k3.y);
        }

        const int col = kt * TK + cbase;
        float4 v0 = make_float4(hsum2(a00), hsum2(a01), hsum2(a02), hsum2(a03));
        float4 v1 = make_float4(hsum2(a10), hsum2(a11), hsum2(a12), hsum2(a13));
        uint32_t sc0 = (uint32_t)__cvta_generic_to_shared(&sc[r0 * PITCH + col]);
        uint32_t sc1 = (uint32_t)__cvta_generic_to_shared(&sc[r1 * PITCH + col]);
        sts128(sc0, v0);
        sts128(sc1, v1);

        __syncthreads();
    }

    // ---- softmax: warp w owns rows 2w and 2w+1 ----
    #pragma unroll
    for (int rr = 0; rr < 2; rr++) {
        const int r = 2 * w + rr;
        float* row = sc + r * PITCH;
        float mx = -1e30f;
        #pragma unroll 8
        for (int i = l; i < LL; i += 32)
            mx = fmaxf(mx, row[i]);
        #pragma unroll
        for (int o = 16; o > 0; o >>= 1)
            mx = fmaxf(mx, __shfl_xor_sync(0xFFFFFFFFu, mx, o));

        float sum = 0.0f;
        #pragma unroll 8
        for (int i = l; i < LL; i += 32) {
            float e = __expf(row[i] - mx);
            row[i] = e;
            sum += e;
        }
        #pragma unroll
        for (int o = 16; o > 0; o >>= 1)
            sum += __shfl_xor_sync(0xFFFFFFFFu, sum, o);

        float inv = 1.0f / sum;
        float* orow = outp + (size_t)r * LL;
        #pragma unroll 8
        for (int i = l; i < LL; i += 32)
            orow[i] = row[i] * inv;
    }
}

extern "C" void kernel_launch(void* const* d_in, const int* in_sizes, int n_in,
                              void* d_out, int out_size) {
    const float* q = (const float*)d_in[0];
    const float* k = (const float*)d_in[1];
    const float* v = (const float*)d_in[2];
    float* out = (float*)d_out;

    const size_t v_elems = (size_t)BB * LL * DD;
    cudaMemcpyAsync(out, v, v_elems * sizeof(float), cudaMemcpyDeviceToDevice);

    cudaFuncSetAttribute(attn_kernel,
                         cudaFuncAttributeMaxDynamicSharedMemorySize,
                         SMEM_BYTES);

    dim3 grid(LL / BQ, BB);   // (128, 16)
    dim3 block(NTHREADS);
    attn_kernel<<<grid, block, SMEM_BYTES>>>(q, k, out + v_elems);
}

// round 5
// speedup vs baseline: 2.6952x; 2.4305x over previous
#include <cuda_runtime.h>
#include <cuda_bf16.h>
#include <cstdint>

#define BB 16
#define LL 2048
#define DDIM 64
#define MT 128          // q rows per CTA
#define NTILE 128       // k cols per tile
#define NTHREADS 256
#define NIT 32          // 2 passes x 16 tiles

// k split-precision scratch (8 MB total)
__device__ __nv_bfloat16 g_k_hi[BB * LL * DDIM];
__device__ __nv_bfloat16 g_k_lo[BB * LL * DDIM];

// ---------------- PTX helpers (all generic-target safe: sm_80+) -------------
__device__ __forceinline__ void cp16(uint32_t dst, const void* src) {
    asm volatile("cp.async.cg.shared.global [%0], [%1], 16;\n" :: "r"(dst), "l"(src));
}
__device__ __forceinline__ void cp_commit() {
    asm volatile("cp.async.commit_group;\n");
}
template <int N>
__device__ __forceinline__ void cp_wait() {
    asm volatile("cp.async.wait_group %0;\n" :: "n"(N));
}

#define LDSM4(r0, r1, r2, r3, addr)                                        \
    asm volatile("ldmatrix.sync.aligned.m8n8.x4.shared.b16 {%0,%1,%2,%3}, [%4];" \
                 : "=r"(r0), "=r"(r1), "=r"(r2), "=r"(r3) : "r"(addr))

#define MMA_BF16(c, a, b0, b1)                                             \
    asm volatile("mma.sync.aligned.m16n8k16.row.col.f32.bf16.bf16.f32 "    \
                 "{%0,%1,%2,%3}, {%4,%5,%6,%7}, {%8,%9}, {%0,%1,%2,%3};"   \
                 : "+f"((c)[0]), "+f"((c)[1]), "+f"((c)[2]), "+f"((c)[3])  \
                 : "r"((a)[0]), "r"((a)[1]), "r"((a)[2]), "r"((a)[3]),     \
                   "r"(b0), "r"(b1))

__device__ __forceinline__ uint32_t pack2(float a, float b) {
    __nv_bfloat162 t = __floats2bfloat162_rn(a, b);   // a -> low half
    return *reinterpret_cast<uint32_t*>(&t);
}
__device__ __forceinline__ uint32_t pack_hi(float2 f) {
    return pack2(f.x, f.y);
}
__device__ __forceinline__ uint32_t pack_lo(float2 f) {
    float hx = __bfloat162float(__float2bfloat16_rn(f.x));
    float hy = __bfloat162float(__float2bfloat16_rn(f.y));
    return pack2(f.x - hx, f.y - hy);
}

// ---------------- kernel 1: k fp32 -> bf16 hi/lo scratch ----------------
__global__ void __launch_bounds__(256)
cvt_k_kernel(const float4* __restrict__ k4) {
    int idx = blockIdx.x * 256 + threadIdx.x;       // 524288 float4s
    float4 f = k4[idx];
    float hx = __bfloat162float(__float2bfloat16_rn(f.x));
    float hy = __bfloat162float(__float2bfloat16_rn(f.y));
    float hz = __bfloat162float(__float2bfloat16_rn(f.z));
    float hw = __bfloat162float(__float2bfloat16_rn(f.w));
    uint2 hi, lo;
    hi.x = pack2(f.x, f.y);            hi.y = pack2(f.z, f.w);
    lo.x = pack2(f.x - hx, f.y - hy);  lo.y = pack2(f.z - hz, f.w - hw);
    reinterpret_cast<uint2*>(g_k_hi)[idx] = hi;
    reinterpret_cast<uint2*>(g_k_lo)[idx] = lo;
}

// ---------------- k tile loader: [buf][mat][n:128][128B], swizzled ----------
__device__ __forceinline__ void load_k_tile(uint32_t sb, int b, int tile,
                                            int buf, int tid) {
    const size_t base = ((size_t)b * LL + (size_t)tile * NTILE) * DDIM;
    #pragma unroll
    for (int rep = 0; rep < 8; rep++) {
        const int m = rep >> 2;                      // 0=hi, 1=lo
        int cidx = tid + (rep & 3) * NTHREADS;       // 0..1023 per matrix
        int n = cidx >> 3, ch = cidx & 7;
        const __nv_bfloat16* src =
            (m ? g_k_lo : g_k_hi) + base + (size_t)n * DDIM + ch * 8;
        uint32_t dst = sb + (uint32_t)buf * 32768u + (uint32_t)m * 16384u
                     + (uint32_t)n * 128u + (uint32_t)((ch ^ (n & 7)) << 4);
        cp16(dst, src);
    }
}

// ---------------- kernel 2: attention ----------------
__global__ void __launch_bounds__(NTHREADS, 2)
attn_mma_kernel(const float* __restrict__ q, float* __restrict__ out_attn) {
    extern __shared__ char smem[];
    const uint32_t sb = (uint32_t)__cvta_generic_to_shared(smem);
    const int tid = threadIdx.x;
    const int w = tid >> 5;
    const int l = tid & 31;
    const int b = blockIdx.y;
    const int qt = blockIdx.x;

    // prologue: k tile 0 and 1 in flight
    load_k_tile(sb, b, 0, 0, tid);
    cp_commit();
    load_k_tile(sb, b, 1, 1, tid);
    cp_commit();

    // A fragments (built once, straight from gmem), m16n8k16 layout:
    // a0=(r, klo) a1=(r+8, klo) a2=(r, khi) a3=(r+8, khi)
    uint32_t ahi[4][4], alo[4][4];
    {
        const float* q0 = q + ((size_t)b * LL + (size_t)qt * MT
                               + w * 16 + (l >> 2)) * DDIM;
        #pragma unroll
        for (int ks = 0; ks < 4; ks++) {
            const int c0 = ks * 16 + (l & 3) * 2;
            float2 p00 = *(const float2*)(q0 + c0);
            float2 p10 = *(const float2*)(q0 + 8 * DDIM + c0);
            float2 p01 = *(const float2*)(q0 + c0 + 8);
            float2 p11 = *(const float2*)(q0 + 8 * DDIM + c0 + 8);
            ahi[ks][0] = pack_hi(p00);  alo[ks][0] = pack_lo(p00);
            ahi[ks][1] = pack_hi(p10);  alo[ks][1] = pack_lo(p10);
            ahi[ks][2] = pack_hi(p01);  alo[ks][2] = pack_lo(p01);
            ahi[ks][3] = pack_hi(p11);  alo[ks][3] = pack_lo(p11);
        }
    }

    // per-lane ldmatrix address pieces
    const int rr = l & 7;          // row within 8-row matrix
    const int mi = l >> 3;         // matrix id 0..3
    const int cs = mi & 1;         // 0 = k-lo chunk, 1 = k-hi chunk
    const int nb = ((mi >> 1) << 3) + rr;   // n offset within 16-col group

    float sum0 = 0.f, sum1 = 0.f, inv0 = 0.f, inv1 = 0.f;
    float* orow0 = out_attn + ((size_t)b * LL + (size_t)qt * MT
                               + w * 16 + (l >> 2)) * (size_t)LL;
    float* orow1 = orow0 + (size_t)8 * LL;

    for (int it = 0; it < NIT; it++) {
        const int buf = it & 1;
        const int tile = it & 15;

        cp_wait<1>();             // current buf's tile resident
        __syncthreads();

        const uint32_t bhiB = sb + (uint32_t)buf * 32768u;
        const uint32_t bloB = bhiB + 16384u;

        #pragma unroll
        for (int half = 0; half < 2; half++) {
            float C[8][4];
            #pragma unroll
            for (int i = 0; i < 8; i++)
                C[i][0] = C[i][1] = C[i][2] = C[i][3] = 0.f;

            #pragma unroll
            for (int j = 0; j < 4; j++) {
                const uint32_t rowoff =
                    (uint32_t)(half * 64 + j * 16 + nb) * 128u;
                #pragma unroll
                for (int ks = 0; ks < 4; ks++) {
                    const uint32_t choff =
                        (uint32_t)((((ks << 1) | cs) ^ rr) << 4);
                    uint32_t h0, h1, h2, h3, e0, e1, e2, e3;
                    LDSM4(h0, h1, h2, h3, bhiB + rowoff + choff);
                    LDSM4(e0, e1, e2, e3, bloB + rowoff + choff);
                    MMA_BF16(C[2 * j],     ahi[ks], h0, h1);
                    MMA_BF16(C[2 * j],     ahi[ks], e0, e1);
                    MMA_BF16(C[2 * j],     alo[ks], h0, h1);
                    MMA_BF16(C[2 * j + 1], ahi[ks], h2, h3);
                    MMA_BF16(C[2 * j + 1], ahi[ks], e2, e3);
                    MMA_BF16(C[2 * j + 1], alo[ks], h2, h3);
                }
            }

            if (it < 16) {
                #pragma unroll
                for (int nf = 0; nf < 8; nf++) {
                    sum0 += __expf(C[nf][0]) + __expf(C[nf][1]);
                    sum1 += __expf(C[nf][2]) + __expf(C[nf][3]);
                }
            } else {
                const int colb = tile * NTILE + half * 64 + ((l & 3) << 1);
                #pragma unroll
                for (int nf = 0; nf < 8; nf++) {
                    float2 v0, v1;
                    v0.x = __expf(C[nf][0]) * inv0;
                    v0.y = __expf(C[nf][1]) * inv0;
                    v1.x = __expf(C[nf][2]) * inv1;
                    v1.y = __expf(C[nf][3]) * inv1;
                    *(float2*)(orow0 + colb + nf * 8) = v0;
                    *(float2*)(orow1 + colb + nf * 8) = v1;
                }
            }
        }

        __syncthreads();          // everyone done reading buf
        if (it + 2 < NIT)
            load_k_tile(sb, b, (it + 2) & 15, buf, tid);
        cp_commit();              // (empty group ok for tail iters)

        if (it == 15) {
            sum0 += __shfl_xor_sync(0xFFFFFFFFu, sum0, 1);
            sum0 += __shfl_xor_sync(0xFFFFFFFFu, sum0, 2);
            sum1 += __shfl_xor_sync(0xFFFFFFFFu, sum1, 1);
            sum1 += __shfl_xor_sync(0xFFFFFFFFu, sum1, 2);
            inv0 = 1.0f / sum0;
            inv1 = 1.0f / sum1;
        }
    }
}

extern "C" void kernel_launch(void* const* d_in, const int* in_sizes, int n_in,
                              void* d_out, int out_size) {
    const float* q = (const float*)d_in[0];
    const float* k = (const float*)d_in[1];
    const float* v = (const float*)d_in[2];
    float* out = (float*)d_out;

    const size_t v_elems = (size_t)BB * LL * DDIM;
    cudaMemcpyAsync(out, v, v_elems * sizeof(float), cudaMemcpyDeviceToDevice);

    cvt_k_kernel<<<(BB * LL * DDIM / 4) / 256, 256>>>((const float4*)k);

    cudaFuncSetAttribute(attn_mma_kernel,
                         cudaFuncAttributeMaxDynamicSharedMemorySize, 65536);
    dim3 grid(LL / MT, BB);   // (16, 16) = 256 CTAs
    attn_mma_kernel<<<grid, NTHREADS, 65536>>>(q, out + v_elems);
}

// round 6
// speedup vs baseline: 2.8305x; 1.0502x over previous
#include <cuda_runtime.h>
#include <cuda_bf16.h>
#include <cstdint>

#define BB 16
#define LL 2048
#define DDIM 64
#define MT 128          // q rows per CTA
#define NTILE 128       // k cols per tile
#define NTHREADS 256
#define NIT 32          // 2 passes x 16 tiles
#define LOG2E 1.4426950408889634f

// k split-precision scratch
__device__ __nv_bfloat16 g_k_hi[BB * LL * DDIM];
__device__ __nv_bfloat16 g_k_lo[BB * LL * DDIM];

// ---------------- PTX helpers (generic-target safe) ----------------
__device__ __forceinline__ void cp16(uint32_t dst, const void* src) {
    asm volatile("cp.async.cg.shared.global [%0], [%1], 16;\n" :: "r"(dst), "l"(src));
}
__device__ __forceinline__ void cp_commit() {
    asm volatile("cp.async.commit_group;\n");
}
template <int N>
__device__ __forceinline__ void cp_wait() {
    asm volatile("cp.async.wait_group %0;\n" :: "n"(N));
}
__device__ __forceinline__ float ex2(float x) {
    float r;
    asm("ex2.approx.f32 %0, %1;" : "=f"(r) : "f"(x));
    return r;
}

#define LDSM4(r0, r1, r2, r3, addr)                                        \
    asm volatile("ldmatrix.sync.aligned.m8n8.x4.shared.b16 {%0,%1,%2,%3}, [%4];" \
                 : "=r"(r0), "=r"(r1), "=r"(r2), "=r"(r3) : "r"(addr))

#define MMA_BF16(c, a, b0, b1)                                             \
    asm volatile("mma.sync.aligned.m16n8k16.row.col.f32.bf16.bf16.f32 "    \
                 "{%0,%1,%2,%3}, {%4,%5,%6,%7}, {%8,%9}, {%0,%1,%2,%3};"   \
                 : "+f"((c)[0]), "+f"((c)[1]), "+f"((c)[2]), "+f"((c)[3])  \
                 : "r"((a)[0]), "r"((a)[1]), "r"((a)[2]), "r"((a)[3]),     \
                   "r"(b0), "r"(b1))

__device__ __forceinline__ uint32_t pack2(float a, float b) {
    __nv_bfloat162 t = __floats2bfloat162_rn(a, b);
    return *reinterpret_cast<uint32_t*>(&t);
}
__device__ __forceinline__ uint32_t pack_hi(float2 f) {
    return pack2(f.x, f.y);
}
__device__ __forceinline__ uint32_t pack_lo(float2 f) {
    float hx = __bfloat162float(__float2bfloat16_rn(f.x));
    float hy = __bfloat162float(__float2bfloat16_rn(f.y));
    return pack2(f.x - hx, f.y - hy);
}

// ---------------- kernel 1: k fp32 -> bf16 hi/lo scratch ----------------
__global__ void __launch_bounds__(256)
cvt_k_kernel(const float4* __restrict__ k4) {
    int idx = blockIdx.x * 256 + threadIdx.x;
    float4 f = k4[idx];
    float hx = __bfloat162float(__float2bfloat16_rn(f.x));
    float hy = __bfloat162float(__float2bfloat16_rn(f.y));
    float hz = __bfloat162float(__float2bfloat16_rn(f.z));
    float hw = __bfloat162float(__float2bfloat16_rn(f.w));
    uint2 hi, lo;
    hi.x = pack2(f.x, f.y);            hi.y = pack2(f.z, f.w);
    lo.x = pack2(f.x - hx, f.y - hy);  lo.y = pack2(f.z - hz, f.w - hw);
    reinterpret_cast<uint2*>(g_k_hi)[idx] = hi;
    reinterpret_cast<uint2*>(g_k_lo)[idx] = lo;
}

// ---------------- k tile loader: [buf:3][mat:2][n:128][128B], swizzled -----
__device__ __forceinline__ void load_k_tile(uint32_t sb, int b, int tile,
                                            int buf, int tid) {
    const size_t base = ((size_t)b * LL + (size_t)tile * NTILE) * DDIM;
    #pragma unroll
    for (int rep = 0; rep < 8; rep++) {
        const int m = rep >> 2;                      // 0=hi, 1=lo
        int cidx = tid + (rep & 3) * NTHREADS;       // 0..1023 per matrix
        int n = cidx >> 3, ch = cidx & 7;
        const __nv_bfloat16* src =
            (m ? g_k_lo : g_k_hi) + base + (size_t)n * DDIM + ch * 8;
        uint32_t dst = sb + (uint32_t)buf * 32768u + (uint32_t)m * 16384u
                     + (uint32_t)n * 128u + (uint32_t)((ch ^ (n & 7)) << 4);
        cp16(dst, src);
    }
}

// ---------------- kernel 2: attention ----------------
__global__ void __launch_bounds__(NTHREADS, 2)
attn_mma_kernel(const float* __restrict__ q, float* __restrict__ out_attn) {
    extern __shared__ char smem[];
    const uint32_t sb = (uint32_t)__cvta_generic_to_shared(smem);
    const int tid = threadIdx.x;
    const int w = tid >> 5;
    const int l = tid & 31;
    const int b = blockIdx.y;
    const int qt = blockIdx.x;

    // prologue: tiles 0,1 in flight
    load_k_tile(sb, b, 0, 0, tid);
    cp_commit();
    load_k_tile(sb, b, 1, 1, tid);
    cp_commit();

    // A fragments (q pre-scaled by log2e, split hi/lo)
    uint32_t ahi[4][4], alo[4][4];
    {
        const float* q0 = q + ((size_t)b * LL + (size_t)qt * MT
                               + w * 16 + (l >> 2)) * DDIM;
        #pragma unroll
        for (int ks = 0; ks < 4; ks++) {
            const int c0 = ks * 16 + (l & 3) * 2;
            float2 p00 = *(const float2*)(q0 + c0);
            float2 p10 = *(const float2*)(q0 + 8 * DDIM + c0);
            float2 p01 = *(const float2*)(q0 + c0 + 8);
            float2 p11 = *(const float2*)(q0 + 8 * DDIM + c0 + 8);
            p00.x *= LOG2E; p00.y *= LOG2E;
            p10.x *= LOG2E; p10.y *= LOG2E;
            p01.x *= LOG2E; p01.y *= LOG2E;
            p11.x *= LOG2E; p11.y *= LOG2E;
            ahi[ks][0] = pack_hi(p00);  alo[ks][0] = pack_lo(p00);
            ahi[ks][1] = pack_hi(p10);  alo[ks][1] = pack_lo(p10);
            ahi[ks][2] = pack_hi(p01);  alo[ks][2] = pack_lo(p01);
            ahi[ks][3] = pack_hi(p11);  alo[ks][3] = pack_lo(p11);
        }
    }

    // per-lane ldmatrix pieces
    const int rr = l & 7;
    const int mi = l >> 3;
    const int cs = mi & 1;
    const int nb = ((mi >> 1) << 3) + rr;

    float s00 = 0.f, s01 = 0.f, s10 = 0.f, s11 = 0.f;
    float inv0 = 0.f, inv1 = 0.f;
    float* orow0 = out_attn + ((size_t)b * LL + (size_t)qt * MT
                               + w * 16 + (l >> 2)) * (size_t)LL;
    float* orow1 = orow0 + (size_t)8 * LL;

    for (int it = 0; it < NIT; it++) {
        const int buf = it % 3;
        const int tile = it & 15;

        cp_wait<1>();
        __syncthreads();

        // issue load(t+2) into buf (t+2)%3 — never read by any warp this iter
        if (it + 2 < NIT)
            load_k_tile(sb, b, (it + 2) & 15, (it + 2) % 3, tid);
        cp_commit();   // uniform one group per iter keeps wait<1> exact

        const uint32_t bhiB = sb + (uint32_t)buf * 32768u;
        const uint32_t bloB = bhiB + 16384u;

        #pragma unroll
        for (int jq = 0; jq < 4; jq++) {       // 32-col quarters
            float C[4][4];
            #pragma unroll
            for (int i = 0; i < 4; i++)
                C[i][0] = C[i][1] = C[i][2] = C[i][3] = 0.f;

            #pragma unroll
            for (int j2 = 0; j2 < 2; j2++) {
                const uint32_t rowoff =
                    (uint32_t)(jq * 32 + j2 * 16 + nb) * 128u;
                #pragma unroll
                for (int ks = 0; ks < 4; ks++) {
                    const uint32_t choff =
                        (uint32_t)((((ks << 1) | cs) ^ rr) << 4);
                    uint32_t h0, h1, h2, h3, e0, e1, e2, e3;
                    LDSM4(h0, h1, h2, h3, bhiB + rowoff + choff);
                    LDSM4(e0, e1, e2, e3, bloB + rowoff + choff);
                    MMA_BF16(C[2 * j2],     ahi[ks], h0, h1);
                    MMA_BF16(C[2 * j2],     ahi[ks], e0, e1);
                    MMA_BF16(C[2 * j2],     alo[ks], h0, h1);
                    MMA_BF16(C[2 * j2 + 1], ahi[ks], h2, h3);
                    MMA_BF16(C[2 * j2 + 1], ahi[ks], e2, e3);
                    MMA_BF16(C[2 * j2 + 1], alo[ks], h2, h3);
                }
            }

            if (it < 16) {
                #pragma unroll
                for (int cf = 0; cf < 4; cf++) {
                    s00 += ex2(C[cf][0]);
                    s01 += ex2(C[cf][1]);
                    s10 += ex2(C[cf][2]);
                    s11 += ex2(C[cf][3]);
                }
            } else {
                const int colb = tile * NTILE + jq * 32 + ((l & 3) << 1);
                #pragma unroll
                for (int cf = 0; cf < 4; cf++) {
                    float2 v0, v1;
                    v0.x = ex2(C[cf][0]) * inv0;
                    v0.y = ex2(C[cf][1]) * inv0;
                    v1.x = ex2(C[cf][2]) * inv1;
                    v1.y = ex2(C[cf][3]) * inv1;
                    *(float2*)(orow0 + colb + cf * 8) = v0;
                    *(float2*)(orow1 + colb + cf * 8) = v1;
                }
            }
        }

        if (it == 15) {
            float sum0 = s00 + s01;
            float sum1 = s10 + s11;
            sum0 += __shfl_xor_sync(0xFFFFFFFFu, sum0, 1);
            sum0 += __shfl_xor_sync(0xFFFFFFFFu, sum0, 2);
            sum1 += __shfl_xor_sync(0xFFFFFFFFu, sum1, 1);
            sum1 += __shfl_xor_sync(0xFFFFFFFFu, sum1, 2);
            inv0 = 1.0f / sum0;
            inv1 = 1.0f / sum1;
        }
    }
}

extern "C" void kernel_launch(void* const* d_in, const int* in_sizes, int n_in,
                              void* d_out, int out_size) {
    const float* q = (const float*)d_in[0];
    const float* k = (const float*)d_in[1];
    const float* v = (const float*)d_in[2];
    float* out = (float*)d_out;

    const size_t v_elems = (size_t)BB * LL * DDIM;
    cudaMemcpyAsync(out, v, v_elems * sizeof(float), cudaMemcpyDeviceToDevice);

    cvt_k_kernel<<<(BB * LL * DDIM / 4) / 256, 256>>>((const float4*)k);

    cudaFuncSetAttribute(attn_mma_kernel,
                         cudaFuncAttributeMaxDynamicSharedMemorySize, 98304);
    dim3 grid(LL / MT, BB);   // (16, 16) = 256 CTAs
    attn_mma_kernel<<<grid, NTHREADS, 98304>>>(q, out + v_elems);
}